// round 9
// baseline (speedup 1.0000x reference)
#include <cuda_runtime.h>
#include <cuda_bf16.h>
#include <math.h>

#define B_DIM 32
#define H_DIM 56
#define W_DIM 56
#define C_DIM 256
#define NPIX (B_DIM * H_DIM * W_DIM)   // 100352
#define HW (H_DIM * W_DIM)             // 3136

#define NCHUNK 4
#define IMGS_PER_CHUNK (B_DIM / NCHUNK)          // 8
#define CHUNK_PIX (IMGS_PER_CHUNK * HW)          // 25088

// Scratch (no cudaMalloc allowed): pooled [avg,max] per pixel.
__device__ float2 g_pooled[NPIX];

// ---------------------------------------------------------------------------
// Kernel 1: channel mean+max pool over one 8-image chunk.
// 4 pixels per warp, 8 lanes per pixel, 4x 32B loads per lane.
// ---------------------------------------------------------------------------
struct f8 { float4 a, b; };
__device__ __forceinline__ f8 ldg_f8(const float* p) {
    f8 r;
    unsigned long long d0, d1, d2, d3;
    asm volatile("ld.global.v4.b64 {%0,%1,%2,%3}, [%4];"
                 : "=l"(d0), "=l"(d1), "=l"(d2), "=l"(d3)
                 : "l"(p));
    r.a.x = __uint_as_float((unsigned)(d0));
    r.a.y = __uint_as_float((unsigned)(d0 >> 32));
    r.a.z = __uint_as_float((unsigned)(d1));
    r.a.w = __uint_as_float((unsigned)(d1 >> 32));
    r.b.x = __uint_as_float((unsigned)(d2));
    r.b.y = __uint_as_float((unsigned)(d2 >> 32));
    r.b.z = __uint_as_float((unsigned)(d3));
    r.b.w = __uint_as_float((unsigned)(d3 >> 32));
    return r;
}

__global__ void __launch_bounds__(256) pool_kernel(const float* __restrict__ x,
                                                   int pix_off) {
    int warp = (blockIdx.x * blockDim.x + threadIdx.x) >> 5;
    int lane = threadIdx.x & 31;
    int sub  = lane >> 3;
    int co   = lane & 7;
    int pix  = pix_off + warp * 4 + sub;

    const float* __restrict__ xr = x + (size_t)pix * C_DIM;
    f8 u0 = ldg_f8(xr + co * 8);
    f8 u1 = ldg_f8(xr + co * 8 + 64);
    f8 u2 = ldg_f8(xr + co * 8 + 128);
    f8 u3 = ldg_f8(xr + co * 8 + 192);

    float4 v0 = u0.a, v1 = u0.b, v2 = u1.a, v3 = u1.b;
    float4 v4 = u2.a, v5 = u2.b, v6 = u3.a, v7 = u3.b;

    float s = (((v0.x + v0.y) + (v0.z + v0.w)) + ((v1.x + v1.y) + (v1.z + v1.w)))
            + (((v2.x + v2.y) + (v2.z + v2.w)) + ((v3.x + v3.y) + (v3.z + v3.w)))
            + (((v4.x + v4.y) + (v4.z + v4.w)) + ((v5.x + v5.y) + (v5.z + v5.w)))
            + (((v6.x + v6.y) + (v6.z + v6.w)) + ((v7.x + v7.y) + (v7.z + v7.w)));

    float m01 = fmaxf(fmaxf(fmaxf(v0.x, v0.y), fmaxf(v0.z, v0.w)),
                      fmaxf(fmaxf(v1.x, v1.y), fmaxf(v1.z, v1.w)));
    float m23 = fmaxf(fmaxf(fmaxf(v2.x, v2.y), fmaxf(v2.z, v2.w)),
                      fmaxf(fmaxf(v3.x, v3.y), fmaxf(v3.z, v3.w)));
    float m45 = fmaxf(fmaxf(fmaxf(v4.x, v4.y), fmaxf(v4.z, v4.w)),
                      fmaxf(fmaxf(v5.x, v5.y), fmaxf(v5.z, v5.w)));
    float m67 = fmaxf(fmaxf(fmaxf(v6.x, v6.y), fmaxf(v6.z, v6.w)),
                      fmaxf(fmaxf(v7.x, v7.y), fmaxf(v7.z, v7.w)));
    float m = fmaxf(fmaxf(m01, m23), fmaxf(m45, m67));

    #pragma unroll
    for (int off = 4; off; off >>= 1) {
        s += __shfl_xor_sync(0xffffffffu, s, off);
        m = fmaxf(m, __shfl_xor_sync(0xffffffffu, m, off));
    }

    if (co == 0) {
        g_pooled[pix] = make_float2(s * (1.0f / 256.0f), m);
    }
}

// ---------------------------------------------------------------------------
// Kernel 2: fused conv + sigmoid + scale for one 8-image chunk.
// One CTA per image-row. Threads 0..55 do the 7x7 conv from L2-hot g_pooled,
// then all 256 threads stream the row's 56KB (x is L2-hot: pooled moments
// ago by the concurrently-running pool chunk pipeline).
// ---------------------------------------------------------------------------
__global__ void __launch_bounds__(256) conv_scale_kernel(
    const float* __restrict__ x,
    const float* __restrict__ w,     // [7,7,2,1] HWIO
    const float* __restrict__ bias,  // [1]
    float* __restrict__ out,
    int img_off)
{
    __shared__ float attn_s[W_DIM];

    int img = img_off + blockIdx.x / H_DIM;
    int row = blockIdx.x % H_DIM;

    const int tid = threadIdx.x;

    // ---- conv phase: threads 0..55, one pixel each ----
    if (tid < W_DIM) {
        const float2* __restrict__ pooled_b = g_pooled + img * HW;
        float acc = __ldg(bias);
        #pragma unroll
        for (int dy = 0; dy < 7; dy++) {
            int gy = row + dy - 3;
            if (gy >= 0 && gy < H_DIM) {
                const float2* __restrict__ prow = pooled_b + gy * W_DIM;
                #pragma unroll
                for (int dx = 0; dx < 7; dx++) {
                    int gx = tid + dx - 3;
                    if (gx >= 0 && gx < W_DIM) {
                        float2 p = __ldg(&prow[gx]);
                        acc = fmaf(p.x, __ldg(&w[(dy * 7 + dx) * 2 + 0]), acc);
                        acc = fmaf(p.y, __ldg(&w[(dy * 7 + dx) * 2 + 1]), acc);
                    }
                }
            }
        }
        attn_s[tid] = 1.0f / (1.0f + __expf(-acc));
    }
    __syncthreads();

    // ---- scale phase: stream the row's 3584 float4 (14 per thread) ----
    const size_t base = ((size_t)img * HW + (size_t)row * W_DIM) * (C_DIM / 4);
    const float4* __restrict__ xr = (const float4*)x;
    float4* __restrict__ o = (float4*)out;

    #pragma unroll
    for (int k = 0; k < 14; k += 7) {
        float4 v[7];
        float  a[7];
        #pragma unroll
        for (int j = 0; j < 7; j++)
            v[j] = __ldcs(&xr[base + tid + (size_t)(k + j) * 256]);
        #pragma unroll
        for (int j = 0; j < 7; j++)
            a[j] = attn_s[(tid + (k + j) * 256) >> 6];
        #pragma unroll
        for (int j = 0; j < 7; j++) {
            v[j].x *= a[j]; v[j].y *= a[j]; v[j].z *= a[j]; v[j].w *= a[j];
        }
        #pragma unroll
        for (int j = 0; j < 7; j++)
            __stcs(&o[base + tid + (size_t)(k + j) * 256], v[j]);
    }
}

extern "C" void kernel_launch(void* const* d_in, const int* in_sizes, int n_in,
                              void* d_out, int out_size) {
    const float* x  = (const float*)d_in[0];
    const float* w  = (const float*)d_in[1];
    const float* b  = (const float*)d_in[2];
    float* out = (float*)d_out;

    // Second stream + events created once, on the first (non-captured,
    // correctness) call. Host-side resources only — no device memory.
    static cudaStream_t s2 = nullptr;
    static cudaEvent_t evP[NCHUNK];
    static cudaEvent_t evJoin;
    if (s2 == nullptr) {
        cudaStreamCreateWithFlags(&s2, cudaStreamNonBlocking);
        for (int i = 0; i < NCHUNK; i++)
            cudaEventCreateWithFlags(&evP[i], cudaEventDisableTiming);
        cudaEventCreateWithFlags(&evJoin, cudaEventDisableTiming);
    }

    const int pool_blocks = (CHUNK_PIX / 4) / 8;          // 784 per chunk
    const int cs_blocks   = IMGS_PER_CHUNK * H_DIM;       // 448 per chunk

    for (int i = 0; i < NCHUNK; i++) {
        pool_kernel<<<pool_blocks, 256, 0, 0>>>(x, i * CHUNK_PIX);
        cudaEventRecord(evP[i], 0);
        cudaStreamWaitEvent(s2, evP[i], 0);
        conv_scale_kernel<<<cs_blocks, 256, 0, s2>>>(
            x, w, b, out, i * IMGS_PER_CHUNK);
    }

    // join s2 back into the capture (default) stream
    cudaEventRecord(evJoin, s2);
    cudaStreamWaitEvent(0, evJoin, 0);
}

// round 10
// speedup vs baseline: 1.0387x; 1.0387x over previous
#include <cuda_runtime.h>
#include <cuda_bf16.h>
#include <math.h>

#define B_DIM 32
#define H_DIM 56
#define W_DIM 56
#define C_DIM 256
#define HW (H_DIM * W_DIM)             // 3136
#define NPIX (B_DIM * HW)              // 100352
#define NROWS (B_DIM * H_DIM)          // 1792 work items (image-rows)
#define ROW_PAD 64                     // pooled row padded to 64 float2 (512B)

// Scratch (no cudaMalloc allowed).
__device__ float2 g_pooled[NROWS * ROW_PAD];  // padded: no line straddles rows
__device__ int    g_row_done[NROWS];
__device__ int    g_ctr[2];                   // [0]=pool claims, [1]=cs claims

// ---------------------------------------------------------------------------
// Reset kernel: zero flags + counters (graph replays need clean state).
// ---------------------------------------------------------------------------
__global__ void reset_kernel() {
    int i = blockIdx.x * blockDim.x + threadIdx.x;
    if (i < NROWS) g_row_done[i] = 0;
    if (i == 0) { g_ctr[0] = 0; g_ctr[1] = 0; }
}

// ---------------------------------------------------------------------------
// Persistent fused kernel. Work item = one image-row.
// Phase A (work-stealing): pool rows -> g_pooled + done flag.
// Phase B (work-stealing): conv+sigmoid+scale rows; spin briefly on the <=7
// row flags needed (guaranteed claimed before any CTA reaches phase B).
// ---------------------------------------------------------------------------
struct f8 { float4 a, b; };
__device__ __forceinline__ f8 ldg_f8(const float* p) {
    f8 r;
    unsigned long long d0, d1, d2, d3;
    asm volatile("ld.global.v4.b64 {%0,%1,%2,%3}, [%4];"
                 : "=l"(d0), "=l"(d1), "=l"(d2), "=l"(d3)
                 : "l"(p));
    r.a.x = __uint_as_float((unsigned)(d0));
    r.a.y = __uint_as_float((unsigned)(d0 >> 32));
    r.a.z = __uint_as_float((unsigned)(d1));
    r.a.w = __uint_as_float((unsigned)(d1 >> 32));
    r.b.x = __uint_as_float((unsigned)(d2));
    r.b.y = __uint_as_float((unsigned)(d2 >> 32));
    r.b.z = __uint_as_float((unsigned)(d3));
    r.b.w = __uint_as_float((unsigned)(d3 >> 32));
    return r;
}

__global__ void __launch_bounds__(256) fused_kernel(
    const float* __restrict__ x,
    const float* __restrict__ w,     // [7,7,2,1] HWIO
    const float* __restrict__ bias,  // [1]
    float* __restrict__ out)
{
    __shared__ int   s_claim;
    __shared__ float attn_s[W_DIM];

    const int tid  = threadIdx.x;
    const int wid  = tid >> 5;
    const int lane = tid & 31;
    const int sub  = lane >> 3;      // pixel within warp's group of 4
    const int co   = lane & 7;       // 32B slot within pixel

    // ================= Phase A: pool rows =================
    for (;;) {
        if (tid == 0) s_claim = atomicAdd(&g_ctr[0], 1);
        __syncthreads();
        int item = s_claim;
        if (item >= NROWS) break;

        const size_t p0 = (size_t)item * W_DIM;   // first pixel of this row

        #pragma unroll
        for (int iter = 0; iter < 2; iter++) {
            int pl = iter * 32 + wid * 4 + sub;   // 0..63 (row has 56)
            if (pl < W_DIM) {
                const float* __restrict__ xr = x + (p0 + pl) * C_DIM;
                f8 u0 = ldg_f8(xr + co * 8);
                f8 u1 = ldg_f8(xr + co * 8 + 64);
                f8 u2 = ldg_f8(xr + co * 8 + 128);
                f8 u3 = ldg_f8(xr + co * 8 + 192);

                float4 v0 = u0.a, v1 = u0.b, v2 = u1.a, v3 = u1.b;
                float4 v4 = u2.a, v5 = u2.b, v6 = u3.a, v7 = u3.b;

                float s = (((v0.x+v0.y)+(v0.z+v0.w)) + ((v1.x+v1.y)+(v1.z+v1.w)))
                        + (((v2.x+v2.y)+(v2.z+v2.w)) + ((v3.x+v3.y)+(v3.z+v3.w)))
                        + (((v4.x+v4.y)+(v4.z+v4.w)) + ((v5.x+v5.y)+(v5.z+v5.w)))
                        + (((v6.x+v6.y)+(v6.z+v6.w)) + ((v7.x+v7.y)+(v7.z+v7.w)));

                float m01 = fmaxf(fmaxf(fmaxf(v0.x,v0.y), fmaxf(v0.z,v0.w)),
                                  fmaxf(fmaxf(v1.x,v1.y), fmaxf(v1.z,v1.w)));
                float m23 = fmaxf(fmaxf(fmaxf(v2.x,v2.y), fmaxf(v2.z,v2.w)),
                                  fmaxf(fmaxf(v3.x,v3.y), fmaxf(v3.z,v3.w)));
                float m45 = fmaxf(fmaxf(fmaxf(v4.x,v4.y), fmaxf(v4.z,v4.w)),
                                  fmaxf(fmaxf(v5.x,v5.y), fmaxf(v5.z,v5.w)));
                float m67 = fmaxf(fmaxf(fmaxf(v6.x,v6.y), fmaxf(v6.z,v6.w)),
                                  fmaxf(fmaxf(v7.x,v7.y), fmaxf(v7.z,v7.w)));
                float m = fmaxf(fmaxf(m01, m23), fmaxf(m45, m67));

                #pragma unroll
                for (int off = 4; off; off >>= 1) {
                    s += __shfl_xor_sync(0xffffffffu, s, off);
                    m = fmaxf(m, __shfl_xor_sync(0xffffffffu, m, off));
                }

                if (co == 0)
                    g_pooled[item * ROW_PAD + pl] =
                        make_float2(s * (1.0f / 256.0f), m);
            }
        }

        __syncthreads();                      // all row writes done
        if (tid == 0) {
            __threadfence();                  // publish pooled data
            atomicExch(&g_row_done[item], 1); // release flag
        }
        __syncthreads();                      // protect s_claim reuse
    }

    // ================= Phase B: conv + sigmoid + scale rows =================
    for (;;) {
        if (tid == 0) s_claim = atomicAdd(&g_ctr[1], 1);
        __syncthreads();
        int item = s_claim;
        if (item >= NROWS) break;

        int img = item / H_DIM;
        int row = item - img * H_DIM;

        // wait for the <=7 pooled rows this conv needs (all already claimed)
        if (tid < 7) {
            int rr = row - 3 + tid;
            if (rr >= 0 && rr < H_DIM) {
                volatile int* f = &g_row_done[img * H_DIM + rr];
                while (*f == 0) { }
            }
        }
        __syncthreads();
        __threadfence();                      // acquire pooled data

        // conv: threads 0..55, one output pixel each
        if (tid < W_DIM) {
            float acc = __ldg(bias);
            #pragma unroll
            for (int dy = 0; dy < 7; dy++) {
                int gy = row + dy - 3;
                if (gy >= 0 && gy < H_DIM) {
                    const float2* prow = g_pooled + (size_t)(img * H_DIM + gy) * ROW_PAD;
                    #pragma unroll
                    for (int dx = 0; dx < 7; dx++) {
                        int gx = tid + dx - 3;
                        if (gx >= 0 && gx < W_DIM) {
                            float2 p = prow[gx];
                            acc = fmaf(p.x, __ldg(&w[(dy * 7 + dx) * 2 + 0]), acc);
                            acc = fmaf(p.y, __ldg(&w[(dy * 7 + dx) * 2 + 1]), acc);
                        }
                    }
                }
            }
            attn_s[tid] = 1.0f / (1.0f + __expf(-acc));
        }
        __syncthreads();

        // scale: stream this row's 3584 float4 (14 per thread)
        const size_t base = ((size_t)img * HW + (size_t)row * W_DIM) * (C_DIM / 4);
        const float4* __restrict__ xr = (const float4*)x;
        float4* __restrict__ o = (float4*)out;

        #pragma unroll
        for (int k = 0; k < 14; k += 7) {
            float4 v[7];
            float  a[7];
            #pragma unroll
            for (int j = 0; j < 7; j++)
                v[j] = __ldcs(&xr[base + tid + (size_t)(k + j) * 256]);
            #pragma unroll
            for (int j = 0; j < 7; j++)
                a[j] = attn_s[(tid + (k + j) * 256) >> 6];
            #pragma unroll
            for (int j = 0; j < 7; j++) {
                v[j].x *= a[j]; v[j].y *= a[j]; v[j].z *= a[j]; v[j].w *= a[j];
            }
            #pragma unroll
            for (int j = 0; j < 7; j++)
                __stcs(&o[base + tid + (size_t)(k + j) * 256], v[j]);
        }
        __syncthreads();                      // protect s_claim + attn_s reuse
    }
}

extern "C" void kernel_launch(void* const* d_in, const int* in_sizes, int n_in,
                              void* d_out, int out_size) {
    const float* x  = (const float*)d_in[0];
    const float* w  = (const float*)d_in[1];
    const float* b  = (const float*)d_in[2];
    float* out = (float*)d_out;

    reset_kernel<<<(NROWS + 255) / 256, 256>>>();

    // Persistent-ish grid; work-stealing makes any grid size deadlock-free.
    fused_kernel<<<896, 256>>>(x, w, b, out);
}

// round 11
// speedup vs baseline: 1.0847x; 1.0443x over previous
#include <cuda_runtime.h>
#include <cuda_bf16.h>
#include <math.h>

#define B_DIM 32
#define H_DIM 56
#define W_DIM 56
#define C_DIM 256
#define HW (H_DIM * W_DIM)             // 3136
#define NPIX (B_DIM * HW)              // 100352
#define NROWS (B_DIM * H_DIM)          // 1792 work items (image-rows)
#define ROW_PAD 64                     // pooled row padded to 64 float2 (512B)

#define GRID_CTAS 592                  // 148 SMs x 4 -> all resident
#define POOL_CTAS 296                  // producer half

// Scratch (no cudaMalloc allowed).
__device__ float2 g_pooled[NROWS * ROW_PAD];
__device__ int    g_row_done[NROWS];
__device__ int    g_ctr[2];            // [0]=pool claims, [1]=cs claims

__global__ void reset_kernel() {
    int i = blockIdx.x * blockDim.x + threadIdx.x;
    if (i < NROWS) g_row_done[i] = 0;
    if (i == 0) { g_ctr[0] = 0; g_ctr[1] = 0; }
}

struct f8 { float4 a, b; };
__device__ __forceinline__ f8 ldg_f8(const float* p) {
    f8 r;
    unsigned long long d0, d1, d2, d3;
    asm volatile("ld.global.v4.b64 {%0,%1,%2,%3}, [%4];"
                 : "=l"(d0), "=l"(d1), "=l"(d2), "=l"(d3)
                 : "l"(p));
    r.a.x = __uint_as_float((unsigned)(d0));
    r.a.y = __uint_as_float((unsigned)(d0 >> 32));
    r.a.z = __uint_as_float((unsigned)(d1));
    r.a.w = __uint_as_float((unsigned)(d1 >> 32));
    r.b.x = __uint_as_float((unsigned)(d2));
    r.b.y = __uint_as_float((unsigned)(d2 >> 32));
    r.b.z = __uint_as_float((unsigned)(d3));
    r.b.w = __uint_as_float((unsigned)(d3 >> 32));
    return r;
}

// ---------------------------------------------------------------------------
// Role-split persistent kernel, all CTAs resident.
//  CTAs [0, POOL_CTAS): drain pool counter (producer), then fall through to
//                       the CS counter (no tail).
//  CTAs [POOL_CTAS, GRID): drain CS counter (consumer) from the start,
//                       spinning briefly on needed row flags.
// Producers are always resident -> consumer spins always make progress.
// Both claim rows in the same global order -> CS trails pool by a small lag
// -> CS x-reads are L2-hot AND pool-reads/CS-writes overlap at the DRAM pipe.
// ---------------------------------------------------------------------------
__global__ void __launch_bounds__(256, 4) fused_kernel(
    const float* __restrict__ x,
    const float* __restrict__ w,     // [7,7,2,1] HWIO
    const float* __restrict__ bias,  // [1]
    float* __restrict__ out)
{
    __shared__ int   s_claim;
    __shared__ float attn_s[W_DIM];

    const int tid  = threadIdx.x;
    const int wid  = tid >> 5;
    const int lane = tid & 31;
    const int sub  = lane >> 3;      // pixel within warp's group of 4
    const int co   = lane & 7;       // 32B slot within pixel

    // ================= producer: pool rows =================
    if (blockIdx.x < POOL_CTAS) {
        for (;;) {
            if (tid == 0) s_claim = atomicAdd(&g_ctr[0], 1);
            __syncthreads();
            int item = s_claim;
            if (item >= NROWS) break;

            const size_t p0 = (size_t)item * W_DIM;

            #pragma unroll
            for (int iter = 0; iter < 2; iter++) {
                int pl = iter * 32 + wid * 4 + sub;   // 0..63 (row has 56)
                if (pl < W_DIM) {
                    const float* __restrict__ xr = x + (p0 + pl) * C_DIM;
                    f8 u0 = ldg_f8(xr + co * 8);
                    f8 u1 = ldg_f8(xr + co * 8 + 64);
                    f8 u2 = ldg_f8(xr + co * 8 + 128);
                    f8 u3 = ldg_f8(xr + co * 8 + 192);

                    float4 v0 = u0.a, v1 = u0.b, v2 = u1.a, v3 = u1.b;
                    float4 v4 = u2.a, v5 = u2.b, v6 = u3.a, v7 = u3.b;

                    float s = (((v0.x+v0.y)+(v0.z+v0.w)) + ((v1.x+v1.y)+(v1.z+v1.w)))
                            + (((v2.x+v2.y)+(v2.z+v2.w)) + ((v3.x+v3.y)+(v3.z+v3.w)))
                            + (((v4.x+v4.y)+(v4.z+v4.w)) + ((v5.x+v5.y)+(v5.z+v5.w)))
                            + (((v6.x+v6.y)+(v6.z+v6.w)) + ((v7.x+v7.y)+(v7.z+v7.w)));

                    float m01 = fmaxf(fmaxf(fmaxf(v0.x,v0.y), fmaxf(v0.z,v0.w)),
                                      fmaxf(fmaxf(v1.x,v1.y), fmaxf(v1.z,v1.w)));
                    float m23 = fmaxf(fmaxf(fmaxf(v2.x,v2.y), fmaxf(v2.z,v2.w)),
                                      fmaxf(fmaxf(v3.x,v3.y), fmaxf(v3.z,v3.w)));
                    float m45 = fmaxf(fmaxf(fmaxf(v4.x,v4.y), fmaxf(v4.z,v4.w)),
                                      fmaxf(fmaxf(v5.x,v5.y), fmaxf(v5.z,v5.w)));
                    float m67 = fmaxf(fmaxf(fmaxf(v6.x,v6.y), fmaxf(v6.z,v6.w)),
                                      fmaxf(fmaxf(v7.x,v7.y), fmaxf(v7.z,v7.w)));
                    float m = fmaxf(fmaxf(m01, m23), fmaxf(m45, m67));

                    #pragma unroll
                    for (int off = 4; off; off >>= 1) {
                        s += __shfl_xor_sync(0xffffffffu, s, off);
                        m = fmaxf(m, __shfl_xor_sync(0xffffffffu, m, off));
                    }

                    if (co == 0)
                        g_pooled[item * ROW_PAD + pl] =
                            make_float2(s * (1.0f / 256.0f), m);
                }
            }

            __syncthreads();
            if (tid == 0) {
                __threadfence();
                atomicExch(&g_row_done[item], 1);
            }
            __syncthreads();
        }
    }

    // ================= consumer: conv + sigmoid + scale =================
    for (;;) {
        if (tid == 0) s_claim = atomicAdd(&g_ctr[1], 1);
        __syncthreads();
        int item = s_claim;
        if (item >= NROWS) break;

        int img = item / H_DIM;
        int row = item - img * H_DIM;

        // wait for the <=7 pooled rows this conv needs
        if (tid < 7) {
            int rr = row - 3 + tid;
            if (rr >= 0 && rr < H_DIM) {
                volatile int* f = &g_row_done[img * H_DIM + rr];
                while (*f == 0) { __nanosleep(64); }
            }
        }
        __syncthreads();
        __threadfence();

        // conv: threads 0..55, one output pixel each
        if (tid < W_DIM) {
            float acc = __ldg(bias);
            #pragma unroll
            for (int dy = 0; dy < 7; dy++) {
                int gy = row + dy - 3;
                if (gy >= 0 && gy < H_DIM) {
                    const float2* prow = g_pooled + (size_t)(img * H_DIM + gy) * ROW_PAD;
                    #pragma unroll
                    for (int dx = 0; dx < 7; dx++) {
                        int gx = tid + dx - 3;
                        if (gx >= 0 && gx < W_DIM) {
                            float2 p = prow[gx];
                            acc = fmaf(p.x, __ldg(&w[(dy * 7 + dx) * 2 + 0]), acc);
                            acc = fmaf(p.y, __ldg(&w[(dy * 7 + dx) * 2 + 1]), acc);
                        }
                    }
                }
            }
            attn_s[tid] = 1.0f / (1.0f + __expf(-acc));
        }
        __syncthreads();

        // scale: stream this row's 3584 float4 (14 per thread)
        const size_t base = ((size_t)img * HW + (size_t)row * W_DIM) * (C_DIM / 4);
        const float4* __restrict__ xr = (const float4*)x;
        float4* __restrict__ o = (float4*)out;

        #pragma unroll
        for (int k = 0; k < 14; k += 7) {
            float4 v[7];
            float  a[7];
            #pragma unroll
            for (int j = 0; j < 7; j++)
                v[j] = __ldcs(&xr[base + tid + (size_t)(k + j) * 256]);
            #pragma unroll
            for (int j = 0; j < 7; j++)
                a[j] = attn_s[(tid + (k + j) * 256) >> 6];
            #pragma unroll
            for (int j = 0; j < 7; j++) {
                v[j].x *= a[j]; v[j].y *= a[j]; v[j].z *= a[j]; v[j].w *= a[j];
            }
            #pragma unroll
            for (int j = 0; j < 7; j++)
                __stcs(&o[base + tid + (size_t)(k + j) * 256], v[j]);
        }
        __syncthreads();
    }
}

extern "C" void kernel_launch(void* const* d_in, const int* in_sizes, int n_in,
                              void* d_out, int out_size) {
    const float* x  = (const float*)d_in[0];
    const float* w  = (const float*)d_in[1];
    const float* b  = (const float*)d_in[2];
    float* out = (float*)d_out;

    reset_kernel<<<(NROWS + 255) / 256, 256>>>();
    fused_kernel<<<GRID_CTAS, 256>>>(x, w, b, out);
}